// round 2
// baseline (speedup 1.0000x reference)
#include <cuda_runtime.h>
#include <cstdint>

#define NNODES 100000
#define RELS   8
#define HF     128
#define NNZ_   1600000
#define CAP    128     // max edges kept per destination node (Poisson(16); P(overflow) ~ 0)

// ---- device scratch (static allocation; no cudaMalloc anywhere) ----
__device__ float g_h[(size_t)RELS * NNODES * HF];   // 409.6 MB : h[r][n][j] = (nodes @ W_r^T)
__device__ int   g_cnt[NNODES];                     // per-dst edge counts
__device__ int2  g_bucket[(size_t)NNODES * CAP];    // 102.4 MB : {src | rel<<17, bits(val)}

// ============================================================================
// Phase 1: bucket edges by destination node (atomic append)
// indices are INT32 (jax x64 is disabled; .astype(int64) is a silent no-op)
// ============================================================================
__global__ void build_buckets(const int* __restrict__ rows,
                              const int* __restrict__ cols,
                              const float* __restrict__ vals) {
    int e = blockIdx.x * blockDim.x + threadIdx.x;
    if (e >= NNZ_) return;
    int row = rows[e];                     // in [0, N*R)
    int rel = row / NNODES;
    int dst = row - rel * NNODES;
    int src = cols[e];
    // range guard: misreads become a rel_err signal instead of a crash
    if ((unsigned)rel >= RELS || (unsigned)dst >= NNODES || (unsigned)src >= NNODES) return;
    int slot = atomicAdd(&g_cnt[dst], 1);
    if (slot < CAP) {
        g_bucket[(size_t)dst * CAP + slot] =
            make_int2(src | (rel << 17), __float_as_int(vals[e]));
    }
}

// ============================================================================
// Phase 2: h[r] = nodes @ W_r^T  (fp32 SIMT GEMM, NT: both operands K-major)
// block tile: 64 (m) x 128 (j), K-steps of 32; 256 threads, 4x8 micro-tile
// ============================================================================
#define BM 64
#define BK 32

__global__ __launch_bounds__(256) void gemm_h(const float* __restrict__ nodes,
                                              const float* __restrict__ W) {
    __shared__ float As[BK][BM + 4];     // [k][m], padded
    __shared__ float Bs[BK][HF + 4];     // [k][j], padded

    const int rel    = blockIdx.y;
    const int m_base = blockIdx.x * BM;
    const int tid    = threadIdx.x;
    const int tm = (tid >> 4) * 4;       // 0..60  (m offset)
    const int tj = (tid & 15) * 8;       // 0..120 (j offset)

    float acc[4][8];
#pragma unroll
    for (int i = 0; i < 4; i++)
#pragma unroll
        for (int j = 0; j < 8; j++) acc[i][j] = 0.f;

    const float* Wr = W + (size_t)rel * HF * HF;

    const int lrow  = tid >> 3;          // 0..31
    const int lquad = (tid & 7) * 4;     // 0,4,...,28  (k offset within tile)

    for (int kt = 0; kt < HF; kt += BK) {
        // load A tile: nodes[m_base + m][kt + k] -> As[k][m]   (coalesced float4)
#pragma unroll
        for (int rr = 0; rr < 2; rr++) {
            int m  = lrow + rr * 32;
            int gm = m_base + m;
            float4 v = make_float4(0.f, 0.f, 0.f, 0.f);
            if (gm < NNODES)
                v = *(const float4*)(nodes + (size_t)gm * HF + kt + lquad);
            As[lquad + 0][m] = v.x; As[lquad + 1][m] = v.y;
            As[lquad + 2][m] = v.z; As[lquad + 3][m] = v.w;
        }
        // load B tile: W[rel][j][kt + k] -> Bs[k][j]
#pragma unroll
        for (int rr = 0; rr < 4; rr++) {
            int j = lrow + rr * 32;
            float4 v = *(const float4*)(Wr + (size_t)j * HF + kt + lquad);
            Bs[lquad + 0][j] = v.x; Bs[lquad + 1][j] = v.y;
            Bs[lquad + 2][j] = v.z; Bs[lquad + 3][j] = v.w;
        }
        __syncthreads();

#pragma unroll
        for (int kk = 0; kk < BK; kk++) {
            float4 a4 = *(const float4*)&As[kk][tm];
            float4 b0 = *(const float4*)&Bs[kk][tj];
            float4 b1 = *(const float4*)&Bs[kk][tj + 4];
            float av[4] = {a4.x, a4.y, a4.z, a4.w};
            float bv[8] = {b0.x, b0.y, b0.z, b0.w, b1.x, b1.y, b1.z, b1.w};
#pragma unroll
            for (int i = 0; i < 4; i++)
#pragma unroll
                for (int j = 0; j < 8; j++)
                    acc[i][j] += av[i] * bv[j];
        }
        __syncthreads();
    }

    // store h[rel][m][tj..tj+7]
#pragma unroll
    for (int i = 0; i < 4; i++) {
        int gm = m_base + tm + i;
        if (gm < NNODES) {
            float* hp = g_h + ((size_t)rel * NNODES + gm) * HF + tj;
            *(float4*)(hp)     = make_float4(acc[i][0], acc[i][1], acc[i][2], acc[i][3]);
            *(float4*)(hp + 4) = make_float4(acc[i][4], acc[i][5], acc[i][6], acc[i][7]);
        }
    }
}

// ============================================================================
// Phase 3: one warp per destination node:
//   out[dst][:] = relu( sum_{edges->dst} val * h[rel][src][:] )
// lane holds features [lane*4, lane*4+4)
// ============================================================================
__global__ __launch_bounds__(256) void aggregate(float* __restrict__ out) {
    int warp = (blockIdx.x * blockDim.x + threadIdx.x) >> 5;
    int lane = threadIdx.x & 31;
    if (warp >= NNODES) return;

    int cnt = g_cnt[warp];
    if (cnt > CAP) cnt = CAP;

    float4 acc = make_float4(0.f, 0.f, 0.f, 0.f);
    const int2* bk = g_bucket + (size_t)warp * CAP;

    for (int s = 0; s < cnt; s++) {
        int2 ent = bk[s];                       // uniform across warp (broadcast)
        int   src = ent.x & 0x1FFFF;
        int   rel = ent.x >> 17;
        float val = __int_as_float(ent.y);
        const float4 hv =
            *(const float4*)(g_h + ((size_t)rel * NNODES + src) * HF + lane * 4);
        acc.x += val * hv.x;
        acc.y += val * hv.y;
        acc.z += val * hv.z;
        acc.w += val * hv.w;
    }

    float4* op = (float4*)(out + (size_t)warp * HF) + lane;
    *op = make_float4(fmaxf(acc.x, 0.f), fmaxf(acc.y, 0.f),
                      fmaxf(acc.z, 0.f), fmaxf(acc.w, 0.f));
}

// ============================================================================
extern "C" void kernel_launch(void* const* d_in, const int* in_sizes, int n_in,
                              void* d_out, int out_size) {
    const float* nodes = (const float*)d_in[0];
    const int*   idx   = (const int*)d_in[1];     // [2, NNZ] int32 (jax x64 off)
    const float* vals  = (const float*)d_in[2];
    const float* W     = (const float*)d_in[3];   // [R, HF, HTO]
    float*       out   = (float*)d_out;

    void* cntp = nullptr;
    cudaGetSymbolAddress(&cntp, g_cnt);
    cudaMemsetAsync(cntp, 0, NNODES * sizeof(int));

    build_buckets<<<(NNZ_ + 255) / 256, 256>>>(idx, idx + NNZ_, vals);
    gemm_h<<<dim3((NNODES + BM - 1) / BM, RELS), 256>>>(nodes, W);
    aggregate<<<(NNODES * 32 + 255) / 256, 256>>>(out);
}

// round 4
// speedup vs baseline: 2.2126x; 2.2126x over previous
#include <cuda_runtime.h>
#include <cuda_bf16.h>
#include <cstdint>

#define NNODES 100000
#define RELS   8
#define HF     128
#define NNZ_   1600000
#define CAP    128
#define TILES_M ((NNODES + 127) / 128)   // 782

// ---- static device scratch ----
__device__ int   g_cnt[NNODES];
__device__ int2  g_bucket[(size_t)NNODES * CAP];                 // {src | rel<<17, bits(val)}
__device__ __nv_bfloat16 g_ah[(size_t)RELS * NNODES * HF];       // agg hi (bf16)
__device__ __nv_bfloat16 g_al[(size_t)RELS * NNODES * HF];       // agg lo (bf16 residual)
__device__ __nv_bfloat16 g_bh[RELS * HF * HF];                   // W hi
__device__ __nv_bfloat16 g_bl[RELS * HF * HF];                   // W lo

// ============================================================================
// helpers (family-portable PTX only: cp.async, ldmatrix, mma.sync — no tcgen05)
// ============================================================================
__device__ __forceinline__ uint32_t smem_u32(const void* p) {
    uint32_t a;
    asm("{ .reg .u64 t; cvta.to.shared.u64 t, %1; cvt.u32.u64 %0, t; }" : "=r"(a) : "l"(p));
    return a;
}
__device__ __forceinline__ void cp16(uint32_t dst, const void* src) {
    asm volatile("cp.async.cg.shared.global [%0], [%1], 16;" :: "r"(dst), "l"(src) : "memory");
}
__device__ __forceinline__ void cp16z(uint32_t dst, const void* src, bool ok) {
    int n = ok ? 16 : 0;   // src-size 0 -> zero-fill, src not read
    asm volatile("cp.async.cg.shared.global [%0], [%1], 16, %2;" :: "r"(dst), "l"(src), "r"(n) : "memory");
}
#define CP_COMMIT() asm volatile("cp.async.commit_group;" ::: "memory")
#define CP_WAIT(N)  asm volatile("cp.async.wait_group %0;" :: "n"(N) : "memory")

__device__ __forceinline__ void ldm_x4(uint32_t& r0, uint32_t& r1, uint32_t& r2, uint32_t& r3, uint32_t a) {
    asm volatile("ldmatrix.sync.aligned.m8n8.x4.shared.b16 {%0,%1,%2,%3}, [%4];"
                 : "=r"(r0), "=r"(r1), "=r"(r2), "=r"(r3) : "r"(a));
}
__device__ __forceinline__ void mma16816(float* c, const uint32_t* a, const uint32_t* b) {
    asm volatile("mma.sync.aligned.m16n8k16.row.col.f32.bf16.bf16.f32 "
                 "{%0,%1,%2,%3}, {%4,%5,%6,%7}, {%8,%9}, {%0,%1,%2,%3};"
                 : "+f"(c[0]), "+f"(c[1]), "+f"(c[2]), "+f"(c[3])
                 : "r"(a[0]), "r"(a[1]), "r"(a[2]), "r"(a[3]), "r"(b[0]), "r"(b[1]));
}

// ============================================================================
// Phase 1: bucket edges by destination (indices are int32)
// ============================================================================
__global__ void build_buckets(const int* __restrict__ rows,
                              const int* __restrict__ cols,
                              const float* __restrict__ vals) {
    int e = blockIdx.x * blockDim.x + threadIdx.x;
    if (e >= NNZ_) return;
    int row = rows[e];
    int rel = row / NNODES;
    int dst = row - rel * NNODES;
    int src = cols[e];
    if ((unsigned)rel >= RELS || (unsigned)dst >= NNODES || (unsigned)src >= NNODES) return;
    int slot = atomicAdd(&g_cnt[dst], 1);
    if (slot < CAP)
        g_bucket[(size_t)dst * CAP + slot] = make_int2(src | (rel << 17), __float_as_int(vals[e]));
}

// ============================================================================
// Phase 1b: split W (fp32 -> bf16 hi/lo)
// ============================================================================
__global__ void convert_w(const float* __restrict__ W) {
    int i = blockIdx.x * blockDim.x + threadIdx.x;
    if (i >= RELS * HF * HF) return;
    float x = W[i];
    __nv_bfloat16 h = __float2bfloat16_rn(x);
    g_bh[i] = h;
    g_bl[i] = __float2bfloat16_rn(x - __bfloat162float(h));
}

// ============================================================================
// Phase 2: one warp per dst: agg[r][dst][:] = sum val * nodes[src][:]
//          gathers hit L2 (nodes = 51MB); store bf16 hi/lo split
// ============================================================================
__device__ __forceinline__ void split_store(int rel, int dst, int lane, float4 a) {
    size_t base = ((size_t)rel * NNODES + dst) * HF + lane * 4;
    __nv_bfloat16 hx = __float2bfloat16_rn(a.x), hy = __float2bfloat16_rn(a.y);
    __nv_bfloat16 hz = __float2bfloat16_rn(a.z), hw = __float2bfloat16_rn(a.w);
    *(__nv_bfloat162*)(g_ah + base)     = __nv_bfloat162(hx, hy);
    *(__nv_bfloat162*)(g_ah + base + 2) = __nv_bfloat162(hz, hw);
    *(__nv_bfloat162*)(g_al + base) = __nv_bfloat162(
        __float2bfloat16_rn(a.x - __bfloat162float(hx)),
        __float2bfloat16_rn(a.y - __bfloat162float(hy)));
    *(__nv_bfloat162*)(g_al + base + 2) = __nv_bfloat162(
        __float2bfloat16_rn(a.z - __bfloat162float(hz)),
        __float2bfloat16_rn(a.w - __bfloat162float(hw)));
}

__global__ __launch_bounds__(256) void aggregate_feats(const float* __restrict__ nodes) {
    int warp = (blockIdx.x * blockDim.x + threadIdx.x) >> 5;
    int lane = threadIdx.x & 31;
    if (warp >= NNODES) return;
    int cnt = g_cnt[warp];
    if (cnt > CAP) cnt = CAP;

    float4 a0 = {0,0,0,0}, a1 = {0,0,0,0}, a2 = {0,0,0,0}, a3 = {0,0,0,0};
    float4 a4 = {0,0,0,0}, a5 = {0,0,0,0}, a6 = {0,0,0,0}, a7 = {0,0,0,0};

    const int2* bk = g_bucket + (size_t)warp * CAP;
    for (int s = 0; s < cnt; s++) {
        int2 e = bk[s];
        int   src = e.x & 0x1FFFF;
        int   rel = e.x >> 17;
        float v   = __int_as_float(e.y);
        float4 x = *(const float4*)(nodes + (size_t)src * HF + lane * 4);
        #define ACC(A) { A.x += v * x.x; A.y += v * x.y; A.z += v * x.z; A.w += v * x.w; }
        switch (rel) {
            case 0: ACC(a0); break; case 1: ACC(a1); break;
            case 2: ACC(a2); break; case 3: ACC(a3); break;
            case 4: ACC(a4); break; case 5: ACC(a5); break;
            case 6: ACC(a6); break; case 7: ACC(a7); break;
        }
        #undef ACC
    }
    split_store(0, warp, lane, a0); split_store(1, warp, lane, a1);
    split_store(2, warp, lane, a2); split_store(3, warp, lane, a3);
    split_store(4, warp, lane, a4); split_store(5, warp, lane, a5);
    split_store(6, warp, lane, a6); split_store(7, warp, lane, a7);
}

// ============================================================================
// Phase 3: out = relu( agg_flat[100k,1024] @ Wcat[128,1024]^T )
// mma.sync m16n8k16 bf16, 3-pass hi/lo split.
// Block tile 128(M) x 128(N); 8 warps in 4(M) x 2(N); warp tile 32x64.
// K streamed in 16 chunks of 64 (2 chunks per relation), 2-stage cp.async.
// SMEM tiles padded to 72-element rows (144B) -> ldmatrix conflict-free.
// ============================================================================
#define PITCH   72                        // bf16 elements per smem row (64 + 8 pad)
#define AT_SZ   (128 * PITCH * 2)         // 18432 B per 128x64 tile
#define SM_A(st, h)  ((uint32_t)((st) * 2 * AT_SZ + (h) * AT_SZ))
#define SM_B(st, h)  ((uint32_t)(4 * AT_SZ + (st) * 2 * AT_SZ + (h) * AT_SZ))
#define SM_TOTAL     (8 * AT_SZ)          // 147456 B

__global__ __launch_bounds__(256, 1) void gemm_out(float* __restrict__ out) {
    extern __shared__ char smem[];
    const uint32_t sb = smem_u32(smem);
    const int tid = threadIdx.x, wid = tid >> 5, lane = tid & 31;
    const int warp_m = wid & 3, warp_n = wid >> 2;
    const int m_base = blockIdx.x * 128;

    // loader: fill one stage with A-hi, A-lo (rows = m), B-hi, B-lo (rows = n)
    auto load_chunk = [&](int kc, int st) {
        int rel  = kc >> 1;
        int koff = (kc & 1) * 64;
        const __nv_bfloat16* pah = g_ah + (size_t)rel * NNODES * HF + koff;
        const __nv_bfloat16* pal = g_al + (size_t)rel * NNODES * HF + koff;
        const __nv_bfloat16* pbh = g_bh + rel * HF * HF + koff;
        const __nv_bfloat16* pbl = g_bl + rel * HF * HF + koff;
        #pragma unroll
        for (int it = 0; it < 4; it++) {
            int id  = it * 256 + tid;         // 0..1023
            int row = id >> 3;                // 0..127
            int col = (id & 7) * 8;           // 0..56
            uint32_t doff = (uint32_t)(row * PITCH + col) * 2;
            int gr = m_base + row;
            bool ok = gr < NNODES;
            size_t moff = (size_t)(ok ? gr : 0) * HF + col;
            cp16z(sb + SM_A(st, 0) + doff, pah + moff, ok);
            cp16z(sb + SM_A(st, 1) + doff, pal + moff, ok);
            size_t noff = (size_t)row * HF + col;
            cp16(sb + SM_B(st, 0) + doff, pbh + noff);
            cp16(sb + SM_B(st, 1) + doff, pbl + noff);
        }
    };

    float acc[2][8][4];
    #pragma unroll
    for (int mt = 0; mt < 2; mt++)
        #pragma unroll
        for (int ng = 0; ng < 8; ng++)
            #pragma unroll
            for (int q = 0; q < 4; q++) acc[mt][ng][q] = 0.f;

    load_chunk(0, 0); CP_COMMIT();
    int st = 0;

    // ldmatrix lane addressing (constant across ksteps except k offset)
    const int a_mrow = warp_m * 32 + ((lane >> 3) & 1) * 8 + (lane & 7);   // + mt*16
    const int a_kcol = ((lane >> 4) & 1) * 8;                              // + ks*16
    const int b_nrow0 = warp_n * 64 + ((lane >> 4) & 1) * 8 + (lane & 7);  // + g*16
    const int b_kcol  = ((lane >> 3) & 1) * 8;                             // + ks*16

    for (int kc = 0; kc < 16; kc++) {
        if (kc < 15) { load_chunk(kc + 1, st ^ 1); CP_COMMIT(); CP_WAIT(1); }
        else         { CP_WAIT(0); }
        __syncthreads();

        #pragma unroll
        for (int ks = 0; ks < 4; ks++) {
            uint32_t ahf[2][4], alf[2][4], bhf[8][2], blf[8][2];
            #pragma unroll
            for (int mt = 0; mt < 2; mt++) {
                uint32_t ao = (uint32_t)((a_mrow + mt * 16) * PITCH + ks * 16 + a_kcol) * 2;
                ldm_x4(ahf[mt][0], ahf[mt][1], ahf[mt][2], ahf[mt][3], sb + SM_A(st, 0) + ao);
                ldm_x4(alf[mt][0], alf[mt][1], alf[mt][2], alf[mt][3], sb + SM_A(st, 1) + ao);
            }
            #pragma unroll
            for (int g = 0; g < 4; g++) {
                uint32_t bo = (uint32_t)((b_nrow0 + g * 16) * PITCH + ks * 16 + b_kcol) * 2;
                ldm_x4(bhf[g*2][0], bhf[g*2][1], bhf[g*2+1][0], bhf[g*2+1][1], sb + SM_B(st, 0) + bo);
                ldm_x4(blf[g*2][0], blf[g*2][1], blf[g*2+1][0], blf[g*2+1][1], sb + SM_B(st, 1) + bo);
            }
            #pragma unroll
            for (int mt = 0; mt < 2; mt++)
                #pragma unroll
                for (int ng = 0; ng < 8; ng++) {
                    mma16816(acc[mt][ng], ahf[mt], bhf[ng]);
                    mma16816(acc[mt][ng], ahf[mt], blf[ng]);
                    mma16816(acc[mt][ng], alf[mt], bhf[ng]);
                }
        }
        __syncthreads();
        st ^= 1;
    }

    // epilogue: c-frag thread t -> rows (t/4, t/4+8), cols (t%4)*2..+1
    const int er = lane >> 2, ec = (lane & 3) * 2;
    #pragma unroll
    for (int mt = 0; mt < 2; mt++) {
        int r0 = m_base + warp_m * 32 + mt * 16 + er;
        #pragma unroll
        for (int ng = 0; ng < 8; ng++) {
            int c = warp_n * 64 + ng * 8 + ec;
            if (r0 < NNODES)
                *(float2*)(out + (size_t)r0 * HF + c) =
                    make_float2(fmaxf(acc[mt][ng][0], 0.f), fmaxf(acc[mt][ng][1], 0.f));
            if (r0 + 8 < NNODES)
                *(float2*)(out + (size_t)(r0 + 8) * HF + c) =
                    make_float2(fmaxf(acc[mt][ng][2], 0.f), fmaxf(acc[mt][ng][3], 0.f));
        }
    }
}

// ============================================================================
extern "C" void kernel_launch(void* const* d_in, const int* in_sizes, int n_in,
                              void* d_out, int out_size) {
    const float* nodes = (const float*)d_in[0];
    const int*   idx   = (const int*)d_in[1];     // [2, NNZ] int32
    const float* vals  = (const float*)d_in[2];
    const float* W     = (const float*)d_in[3];
    float*       out   = (float*)d_out;

    void* cntp = nullptr;
    cudaGetSymbolAddress(&cntp, g_cnt);
    cudaMemsetAsync(cntp, 0, NNODES * sizeof(int));

    cudaFuncSetAttribute(gemm_out, cudaFuncAttributeMaxDynamicSharedMemorySize, SM_TOTAL);

    build_buckets<<<(NNZ_ + 255) / 256, 256>>>(idx, idx + NNZ_, vals);
    convert_w<<<(RELS * HF * HF + 255) / 256, 256>>>(W);
    aggregate_feats<<<(NNODES * 32 + 255) / 256, 256>>>(nodes);
    gemm_out<<<TILES_M, 256, SM_TOTAL>>>(out);
}